// round 5
// baseline (speedup 1.0000x reference)
#include <cuda_runtime.h>

// vaeVectorQuantizer: x[N=131072, D=64], E[D=64, K=1024]
// Reference argmin key: d = fl( fl(y_sq + e_sq_k) - fl(2*sim_k) )  (all fp32)
// y_sq ~ 64 => distance grid ulp ~ 7.6e-6: ties resolved to lowest index.
// We emulate that rounding exactly: y_sq/e_sq correctly rounded (via double),
// sim in fp32, final key via single-rounding FMA (product -2*sim exact).

#define D_DIM 64
#define K_DIM 1024
#define ROWS_PER_CTA 128
#define KTILE 64
#define NTHREADS 256

__device__ float g_esq[K_DIM];
__device__ float g_ET[K_DIM * D_DIM];  // [k][d] transposed codebook for coalesced gather

__global__ void vq_prep(const float* __restrict__ E) {
    int k = blockIdx.x * blockDim.x + threadIdx.x;
    if (k >= K_DIM) return;
    double s = 0.0;
#pragma unroll
    for (int d = 0; d < D_DIM; ++d) {
        float v = E[d * K_DIM + k];
        s = fma((double)v, (double)v, s);
        g_ET[k * D_DIM + d] = v;
    }
    g_esq[k] = (float)s;   // correctly-rounded fp32 ||e_k||^2
}

__global__ __launch_bounds__(NTHREADS, 2)
void vq_main(const float* __restrict__ x, const float* __restrict__ E,
             float* __restrict__ out) {
    extern __shared__ float smem[];
    float* Xs = smem;           // 64 x 128 floats (transposed x block, swizzled) = 32KB
    float* Es = smem + 8192;    // 64 x 64 floats (E k-tile)                     = 16KB
    // total dynamic smem = 49152 B

    const int tid = threadIdx.x;
    const int rg  = tid >> 4;   // 0..15 row group
    const int cg  = tid & 15;   // 0..15 code group
    const size_t rowbase = (size_t)blockIdx.x * ROWS_PER_CTA;

    // ---- Load X block [128 rows x 64 d] transposed into Xs[d][r] (swizzled),
    //      and accumulate exact (double) per-thread partial row norms.
    const float* xg = x + rowbase * D_DIM;
    double ysq_d[8];
#pragma unroll
    for (int it = 0; it < 8; ++it) {
        int i  = tid + it * NTHREADS;   // float4 index 0..2047
        int r  = i >> 4;                // row = (tid>>4) + 16*it
        int d0 = (i & 15) << 2;         // = (tid&15)*4, constant per thread
        float4 v = *(const float4*)(xg + r * D_DIM + d0);
        int rb = r & ~3, rl = r & 3;
        Xs[(d0+0)*128 + ((rb ^ (((d0+0)&7)<<2)) | rl)] = v.x;
        Xs[(d0+1)*128 + ((rb ^ (((d0+1)&7)<<2)) | rl)] = v.y;
        Xs[(d0+2)*128 + ((rb ^ (((d0+2)&7)<<2)) | rl)] = v.z;
        Xs[(d0+3)*128 + ((rb ^ (((d0+3)&7)<<2)) | rl)] = v.w;
        double p = fma((double)v.x, (double)v.x,
                   fma((double)v.y, (double)v.y,
                   fma((double)v.z, (double)v.z, (double)v.w * (double)v.w)));
        ysq_d[it] = p;
    }
    // Butterfly-reduce row norms over the 16 threads sharing a row group
    // (threads 16g..16g+15 are contiguous lanes; xor 1/2/4/8 stays in-group).
#pragma unroll
    for (int ofs = 8; ofs >= 1; ofs >>= 1) {
#pragma unroll
        for (int it = 0; it < 8; ++it)
            ysq_d[it] += __shfl_xor_sync(0xffffffffu, ysq_d[it], ofs);
    }
    // Publish correctly-rounded fp32 y_sq for rows g+16*it (Es area, pre-loop).
    float* ys_sh = Es;  // 128 floats, transient
    if (cg == 0) {
#pragma unroll
        for (int it = 0; it < 8; ++it)
            ys_sh[rg + 16 * it] = (float)ysq_d[it];
    }
    __syncthreads();
    // Each thread grabs y_sq for its 8 compute rows.
    float ysr[8];
#pragma unroll
    for (int i = 0; i < 4; ++i) {
        ysr[i]     = ys_sh[4 * rg + i];
        ysr[4 + i] = ys_sh[64 + 4 * rg + i];
    }

    float bestv[8];
    int   bestc[8];
#pragma unroll
    for (int i = 0; i < 8; ++i) { bestv[i] = 3.402823466e38f; bestc[i] = 0; }

    for (int k0 = 0; k0 < K_DIM; k0 += KTILE) {
        __syncthreads();   // ys reads / previous-tile Es reads done
#pragma unroll
        for (int it = 0; it < 4; ++it) {
            int i  = tid + it * NTHREADS;
            int d  = i >> 4;
            int kk = (i & 15) << 2;
            *(float4*)&Es[d * KTILE + kk] = *(const float4*)(E + d * K_DIM + k0 + kk);
        }
        __syncthreads();

        float4 esq4 = *(const float4*)(g_esq + k0 + 4 * cg);

        float acc[8][4];
#pragma unroll
        for (int i = 0; i < 8; ++i)
#pragma unroll
            for (int j = 0; j < 4; ++j) acc[i][j] = 0.f;

#pragma unroll 16
        for (int d = 0; d < D_DIM; ++d) {
            int sw = (d & 7) << 2;
            float4 xa = *(float4*)&Xs[d * 128 + ((4 * rg) ^ sw)];
            float4 xb = *(float4*)&Xs[d * 128 + (64 + ((4 * rg) ^ sw))];
            float4 e4 = *(float4*)&Es[d * KTILE + 4 * cg];
            float xr[8] = {xa.x, xa.y, xa.z, xa.w, xb.x, xb.y, xb.z, xb.w};
            float er[4] = {e4.x, e4.y, e4.z, e4.w};
#pragma unroll
            for (int i = 0; i < 8; ++i)
#pragma unroll
                for (int j = 0; j < 4; ++j)
                    acc[i][j] = fmaf(xr[i], er[j], acc[i][j]);
        }

        // ---- argmin with reference-exact rounding:
        // t1 = fl(y_sq + e_sq); key = fl(t1 - 2*acc)  (product -2*acc exact => FMA = fadd)
        float er2[4] = {esq4.x, esq4.y, esq4.z, esq4.w};
#pragma unroll
        for (int j = 0; j < 4; ++j) {
            int c = k0 + 4 * cg + j;
#pragma unroll
            for (int i = 0; i < 8; ++i) {
                float t1  = __fadd_rn(ysr[i], er2[j]);
                float key = fmaf(-2.f, acc[i][j], t1);
                if (key < bestv[i]) { bestv[i] = key; bestc[i] = c; }
            }
        }
    }

    // ---- Cross-thread reduction over the 16 code groups, per row (ties -> lowest idx).
    __syncthreads();
    float* red_v = Es;
    int*   red_i = (int*)(Es + 2048);
#pragma unroll
    for (int i = 0; i < 8; ++i) {
        int r = (i < 4) ? (4 * rg + i) : (64 + 4 * rg + (i - 4));
        red_v[r * 16 + cg] = bestv[i];
        red_i[r * 16 + cg] = bestc[i];
    }
    __syncthreads();
    int* cidx = (int*)Xs;
    if (tid < ROWS_PER_CTA) {
        float bv = red_v[tid * 16];
        int   bc = red_i[tid * 16];
#pragma unroll
        for (int j = 1; j < 16; ++j) {
            float v = red_v[tid * 16 + j];
            int   c = red_i[tid * 16 + j];
            if (v < bv || (v == bv && c < bc)) { bv = v; bc = c; }
        }
        cidx[tid] = bc;
    }
    __syncthreads();

    // ---- Gather output rows from transposed codebook (coalesced both sides).
    float* og = out + rowbase * D_DIM;
#pragma unroll
    for (int it = 0; it < 8; ++it) {
        int i  = tid + it * NTHREADS;
        int r  = i >> 4;
        int d0 = (i & 15) << 2;
        *(float4*)(og + r * D_DIM + d0) =
            *(const float4*)(g_ET + cidx[r] * D_DIM + d0);
    }
}

extern "C" void kernel_launch(void* const* d_in, const int* in_sizes, int n_in,
                              void* d_out, int out_size) {
    const float* x = (const float*)d_in[0];
    const float* E = (const float*)d_in[1];
    float* out = (float*)d_out;
    int N = in_sizes[0] / D_DIM;  // 131072

    vq_prep<<<K_DIM / NTHREADS, NTHREADS>>>(E);
    vq_main<<<N / ROWS_PER_CTA, NTHREADS, 49152>>>(x, E, out);
}

// round 9
// speedup vs baseline: 1.4847x; 1.4847x over previous
#include <cuda_runtime.h>
#include <cuda_bf16.h>
#include <cstdint>

// vaeVectorQuantizer: x[N=131072, D=64], E[D=64, K=1024]
// mma.sync.m16n8k16.bf16 path; sim = sum of 6 limb products of 3-limb bf16
// splits of x and E (cross terms REQUIRED: R7 bug was diagonal-only).
// key = fmaf(-2, sim, fl(y_sq + e_sq)); y_sq/e_sq correctly rounded (double).
// Warps split by column half: 4 warps x (32 rows x 64 cols) -> B smem traffic /2.

#define D_DIM 64
#define K_DIM 1024
#define ROWS_PER_CTA 128
#define NTILE 128
#define NTILES 8
#define NTHREADS 256

#define PADROW 144                             // 128B data + 16B pad (bank stride 4)
#define LIMB_STRIDE (ROWS_PER_CTA * PADROW)    // 18432
#define SM_X     0
#define SM_B     (3 * LIMB_STRIDE)             // 55296
#define B_BYTES  (NTILE * 64 * 3 * 2)          // 49152 (fragment-packed tile)
#define SM_ESQ   (SM_B + B_BYTES)              // 104448
#define SM_YS    (SM_ESQ + 4096)               // 108544
#define SM_MRG   (SM_YS + 512)                 // 109056 (bv0,bc0,bv1,bc1: 4*512)
#define SM_CIDX  (SM_MRG + 2048)               // 111104
#define SM_TOTAL (SM_CIDX + 512)               // 111616

__device__ float g_esq[K_DIM];
__device__ float g_ET[K_DIM * D_DIM];             // [k][d] for coalesced gather
__device__ uint2 g_Bf[NTILES * 4 * 3 * 16 * 32];  // [t][kc][limb][nf][lane]

__device__ __forceinline__ void split3(float f, __nv_bfloat16& b1,
                                       __nv_bfloat16& b2, __nv_bfloat16& b3) {
    b1 = __float2bfloat16(f);
    float r1 = f - __bfloat162float(b1);
    b2 = __float2bfloat16(r1);
    float r2 = r1 - __bfloat162float(b2);
    b3 = __float2bfloat16(r2);
}

__device__ __forceinline__ void mma16816(float* c, uint32_t a0, uint32_t a1,
                                         uint32_t a2, uint32_t a3,
                                         uint32_t b0, uint32_t b1) {
    asm volatile(
        "mma.sync.aligned.m16n8k16.row.col.f32.bf16.bf16.f32 "
        "{%0,%1,%2,%3}, {%4,%5,%6,%7}, {%8,%9}, {%0,%1,%2,%3};"
        : "+f"(c[0]), "+f"(c[1]), "+f"(c[2]), "+f"(c[3])
        : "r"(a0), "r"(a1), "r"(a2), "r"(a3), "r"(b0), "r"(b1));
}

// ---------------- prep: e_sq (double) + transposed gather table ----------------
__global__ void vq_prep(const float* __restrict__ E) {
    int k = blockIdx.x * blockDim.x + threadIdx.x;
    if (k >= K_DIM) return;
    double s = 0.0;
#pragma unroll
    for (int d = 0; d < D_DIM; ++d) {
        float v = E[d * K_DIM + k];
        s = fma((double)v, (double)v, s);
        g_ET[k * D_DIM + d] = v;
    }
    g_esq[k] = (float)s;
}

// ---------------- prep: B limbs packed in mma fragment-lane order ----------------
// Fragment (t,kc,limb,nf), lane l, reg m, half j holds
//   E_limb[d][code],  d = kc*16 + (l%4)*2 + m*8 + j,  code = t*128 + nf*8 + l/4
__global__ void vq_prep_b(const float* __restrict__ E) {
    int idx = blockIdx.x * blockDim.x + threadIdx.x;   // 49152 total
    int lane = idx & 31;
    int x1 = idx >> 5;
    int nf = x1 & 15;
    int x2 = x1 >> 4;
    int limb = x2 % 3;
    int x3 = x2 / 3;
    int kc = x3 & 3;
    int t = x3 >> 2;

    int code = t * 128 + nf * 8 + (lane >> 2);
    int c = lane & 3;
    uint32_t r[2];
#pragma unroll
    for (int m = 0; m < 2; ++m) {
        int d0 = kc * 16 + c * 2 + m * 8;
        __nv_bfloat16 q0[3], q1[3];
        split3(E[d0 * K_DIM + code], q0[0], q0[1], q0[2]);
        split3(E[(d0 + 1) * K_DIM + code], q1[0], q1[1], q1[2]);
        __nv_bfloat162 pk(q0[limb], q1[limb]);
        r[m] = *(uint32_t*)&pk;
    }
    g_Bf[idx] = make_uint2(r[0], r[1]);
}

// ---------------- main ----------------
__global__ __launch_bounds__(NTHREADS, 2)
void vq_tc(const float* __restrict__ x, float* __restrict__ out) {
    extern __shared__ __align__(16) char smem[];
    const int tid = threadIdx.x;
    const int wid = tid >> 5;
    const int lane = tid & 31;
    const size_t rowbase = (size_t)blockIdx.x * ROWS_PER_CTA;

    float* esq_s = (float*)(smem + SM_ESQ);
    float* ys_sh = (float*)(smem + SM_YS);
    int*   cidx  = (int*)(smem + SM_CIDX);

    // e_sq -> smem
    *(float4*)(esq_s + 4 * tid) = *(const float4*)(g_esq + 4 * tid);

    // ---- x: 3-limb bf16 split into padded smem + exact double row norms
    {
        int r = tid >> 1, dh = (tid & 1) * 32;
        const float* xr = x + (rowbase + r) * D_DIM + dh;
        char* xs = smem + SM_X + r * PADROW;
        double s = 0.0;
#pragma unroll
        for (int i = 0; i < 8; ++i) {
            float4 v = *(const float4*)(xr + 4 * i);
            int d0 = dh + 4 * i;
            float vs[4] = {v.x, v.y, v.z, v.w};
            __nv_bfloat16 p1[4], p2[4], p3[4];
#pragma unroll
            for (int e = 0; e < 4; ++e) {
                split3(vs[e], p1[e], p2[e], p3[e]);
                s = fma((double)vs[e], (double)vs[e], s);
            }
#pragma unroll
            for (int h = 0; h < 2; ++h) {
                int off = (d0 + 2 * h) * 2;
                *(__nv_bfloat162*)(xs + off)                   = __nv_bfloat162(p1[2*h], p1[2*h+1]);
                *(__nv_bfloat162*)(xs + off + LIMB_STRIDE)     = __nv_bfloat162(p2[2*h], p2[2*h+1]);
                *(__nv_bfloat162*)(xs + off + 2 * LIMB_STRIDE) = __nv_bfloat162(p3[2*h], p3[2*h+1]);
            }
        }
        s += __shfl_xor_sync(0xffffffffu, s, 1);
        if (!(tid & 1)) ys_sh[r] = (float)s;
    }
    __syncthreads();

    // Column-half split: warps 0-3 -> nf 0-7, warps 4-7 -> nf 8-15.
    // Warp-in-group wg owns rows wg*32 .. wg*32+31 (2 m-fragments).
    const int colhalf = wid >> 2;
    const int wg = wid & 3;
    const int g = lane >> 2, c = lane & 3;

    // row ids per lane: [mf][0]=wg*32+mf*16+g, [mf][1]=+8
    int rowid[2][2];
    float ysr[2][2];
    const char* aRow[2][2];
#pragma unroll
    for (int mf = 0; mf < 2; ++mf)
#pragma unroll
        for (int h = 0; h < 2; ++h) {
            int r = wg * 32 + mf * 16 + h * 8 + g;
            rowid[mf][h] = r;
            ysr[mf][h] = ys_sh[r];
            aRow[mf][h] = smem + SM_X + r * PADROW + c * 4;
        }

    float bv[2][2] = {{3.402823466e38f, 3.402823466e38f},
                      {3.402823466e38f, 3.402823466e38f}};
    int   bc[2][2] = {{0, 0}, {0, 0}};

    const int pp[6] = {0, 0, 1, 0, 1, 2};
    const int qq[6] = {0, 1, 0, 2, 1, 0};

    for (int t = 0; t < NTILES; ++t) {
        // ---- stage fragment-packed B tile (48KB) into smem
        const float4* gB = (const float4*)((const char*)g_Bf + t * B_BYTES);
        float4* sB = (float4*)(smem + SM_B);
#pragma unroll
        for (int i = 0; i < 12; ++i) sB[tid + i * NTHREADS] = __ldg(gB + tid + i * NTHREADS);
        __syncthreads();

        float acc[8][2][4];
#pragma unroll
        for (int nf = 0; nf < 8; ++nf)
#pragma unroll
            for (int mf = 0; mf < 2; ++mf)
#pragma unroll
                for (int j = 0; j < 4; ++j) acc[nf][mf][j] = 0.f;

#pragma unroll
        for (int kc = 0; kc < 4; ++kc) {
#pragma unroll
            for (int pr = 0; pr < 6; ++pr) {
                const int p = pp[pr], q = qq[pr];
                const uint2* bp = (const uint2*)(smem + SM_B + (kc * 3 + q) * 4096)
                                  + colhalf * 256 + lane;
                uint2 B[8];
#pragma unroll
                for (int nf = 0; nf < 8; ++nf) B[nf] = bp[nf * 32];
#pragma unroll
                for (int mf = 0; mf < 2; ++mf) {
                    const char* a0p = aRow[mf][0] + p * LIMB_STRIDE + kc * 32;
                    const char* a1p = aRow[mf][1] + p * LIMB_STRIDE + kc * 32;
                    uint32_t a0 = *(const uint32_t*)(a0p);
                    uint32_t a1 = *(const uint32_t*)(a1p);
                    uint32_t a2 = *(const uint32_t*)(a0p + 16);
                    uint32_t a3 = *(const uint32_t*)(a1p + 16);
#pragma unroll
                    for (int nf = 0; nf < 8; ++nf)
                        mma16816(acc[nf][mf], a0, a1, a2, a3, B[nf].x, B[nf].y);
                }
            }
        }

        // ---- fused argmin epilogue (reference-exact rounding, tie -> lowest idx)
#pragma unroll
        for (int nf = 0; nf < 8; ++nf) {
            int cb = t * NTILE + colhalf * 64 + nf * 8 + 2 * c;
            float e0 = esq_s[cb], e1 = esq_s[cb + 1];
#pragma unroll
            for (int mf = 0; mf < 2; ++mf) {
                float k00 = fmaf(-2.f, acc[nf][mf][0], __fadd_rn(ysr[mf][0], e0));
                float k01 = fmaf(-2.f, acc[nf][mf][1], __fadd_rn(ysr[mf][0], e1));
                float k10 = fmaf(-2.f, acc[nf][mf][2], __fadd_rn(ysr[mf][1], e0));
                float k11 = fmaf(-2.f, acc[nf][mf][3], __fadd_rn(ysr[mf][1], e1));
                if (k00 < bv[mf][0]) { bv[mf][0] = k00; bc[mf][0] = cb; }
                if (k01 < bv[mf][0]) { bv[mf][0] = k01; bc[mf][0] = cb + 1; }
                if (k10 < bv[mf][1]) { bv[mf][1] = k10; bc[mf][1] = cb; }
                if (k11 < bv[mf][1]) { bv[mf][1] = k11; bc[mf][1] = cb + 1; }
            }
        }
        __syncthreads();   // B tile consumed before next stage overwrites
    }

    // ---- merge across the 4 lanes (c) sharing each row (tie -> lowest index)
#pragma unroll
    for (int off = 1; off <= 2; off <<= 1) {
#pragma unroll
        for (int mf = 0; mf < 2; ++mf)
#pragma unroll
            for (int h = 0; h < 2; ++h) {
                float v = __shfl_xor_sync(0xffffffffu, bv[mf][h], off);
                int   cc = __shfl_xor_sync(0xffffffffu, bc[mf][h], off);
                if (v < bv[mf][h] || (v == bv[mf][h] && cc < bc[mf][h])) {
                    bv[mf][h] = v; bc[mf][h] = cc;
                }
            }
    }
    // ---- cross-column-half merge via smem
    float* bv0 = (float*)(smem + SM_MRG);
    int*   bc0 = (int*)(smem + SM_MRG + 512);
    float* bv1 = (float*)(smem + SM_MRG + 1024);
    int*   bc1 = (int*)(smem + SM_MRG + 1536);
    if (c == 0) {
#pragma unroll
        for (int mf = 0; mf < 2; ++mf)
#pragma unroll
            for (int h = 0; h < 2; ++h) {
                int r = rowid[mf][h];
                if (colhalf == 0) { bv0[r] = bv[mf][h]; bc0[r] = bc[mf][h]; }
                else              { bv1[r] = bv[mf][h]; bc1[r] = bc[mf][h]; }
            }
    }
    __syncthreads();
    if (tid < ROWS_PER_CTA) {
        float va = bv0[tid], vb = bv1[tid];
        int   ca = bc0[tid], cb2 = bc1[tid];
        int pickB = (vb < va) || (vb == va && cb2 < ca);
        cidx[tid] = pickB ? cb2 : ca;
    }
    __syncthreads();

    // ---- gather output rows from transposed codebook
    float* og = out + rowbase * D_DIM;
#pragma unroll
    for (int it = 0; it < 8; ++it) {
        int i  = tid + it * NTHREADS;
        int r  = i >> 4;
        int d0 = (i & 15) << 2;
        *(float4*)(og + r * D_DIM + d0) = *(const float4*)(g_ET + cidx[r] * D_DIM + d0);
    }
}

extern "C" void kernel_launch(void* const* d_in, const int* in_sizes, int n_in,
                              void* d_out, int out_size) {
    const float* x = (const float*)d_in[0];
    const float* E = (const float*)d_in[1];
    float* out = (float*)d_out;
    int N = in_sizes[0] / D_DIM;  // 131072

    cudaFuncSetAttribute(vq_tc, cudaFuncAttributeMaxDynamicSharedMemorySize, SM_TOTAL);
    vq_prep<<<K_DIM / NTHREADS, NTHREADS>>>(E);
    vq_prep_b<<<(NTILES * 4 * 3 * 16 * 32) / NTHREADS, NTHREADS>>>(E);
    vq_tc<<<N / ROWS_PER_CTA, NTHREADS, SM_TOTAL>>>(x, out);
}